// round 7
// baseline (speedup 1.0000x reference)
#include <cuda_runtime.h>
#include <cstdint>

// DiverseSiblingsSearch on GB300 — single-DRAM-pass threshold-select, fully fused.
// lprobs: (128, 5, 50257) f32, scores: (128, 5, 10) f32, step: int scalar (=10).
// Output (f32): final_scores (128,10) | final_indices (128,10) | final_beams (128,10).

#define BSZ     128
#define BEAM    5
#define VOCAB   50257
#define KSEL    10
#define ROWS    (BSZ * BEAM)
#define T       256
#define CAP     512
#define DIV_RATE 0.5f
#define NEG_INF __int_as_float(0xff800000u)
#define IDX_INF 0x7fffffff

// Dynamic smem layout: u16 row cache | smax[T] | cval[CAP] | cidx[CAP] | count | pad
#define SU16_BYTES 100544                      // 50260 u16, padded to 16B
#define DSM_BYTES  (SU16_BYTES + T * 4 + CAP * 4 + CAP * 4 + 64)

// Inter-block scratch (no allocations allowed).
__device__ float g_cand_val[ROWS * KSEL];
__device__ int   g_cand_idx[ROWS * KSEL];
__device__ int   g_batch_done[BSZ];            // zero-init; reset by finisher each replay

__device__ __forceinline__ bool better(float v1, int i1, float v2, int i2) {
    // JAX top_k stability: larger value wins; ties -> smaller index wins.
    return (v1 > v2) || (v1 == v2 && i1 < i2);
}

__device__ __forceinline__ float4 max4(float4 a, float4 b) {
    return make_float4(fmaxf(a.x, b.x), fmaxf(a.y, b.y), fmaxf(a.z, b.z), fmaxf(a.w, b.w));
}

// Pack high 16 bits of 4 floats (2x PRMT) and store 8B to smem.
__device__ __forceinline__ void stash4(uint16_t* su16, int v, float4 a) {
    uint32_t lo, hi;
    asm("prmt.b32 %0, %1, %2, 0x7632;" : "=r"(lo)
        : "r"(__float_as_uint(a.x)), "r"(__float_as_uint(a.y)));
    asm("prmt.b32 %0, %1, %2, 0x7632;" : "=r"(hi)
        : "r"(__float_as_uint(a.z)), "r"(__float_as_uint(a.w)));
    *reinterpret_cast<uint2*>(su16 + 4 * v) = make_uint2(lo, hi);
}

__global__ __launch_bounds__(T)
void dss_kernel(const float* __restrict__ lprobs,
                const float* __restrict__ scores,
                const int* __restrict__ step_ptr,
                int score_last_dim,
                float* __restrict__ out) {
    extern __shared__ char dsm[];
    uint16_t* su16   = reinterpret_cast<uint16_t*>(dsm);
    float*    smax   = reinterpret_cast<float*>(dsm + SU16_BYTES);
    float*    cval   = smax + T;
    int*      cidx   = reinterpret_cast<int*>(cval + CAP);
    unsigned* scount = reinterpret_cast<unsigned*>(cidx + CAP);
    float*    sthr   = reinterpret_cast<float*>(scount + 1);

    const int row   = blockIdx.x;                 // row = batch * BEAM + beam
    const int batch = row / BEAM;
    const int tid   = threadIdx.x;
    const int lane  = tid & 31;
    const float* __restrict__ rp = lprobs + (size_t)row * VOCAB;

    if (tid == 0) *scount = 0u;

    // Alignment peel: row*VOCAB mod 4 == row mod 4.
    const int P     = (4 - (row & 3)) & 3;        // head elements (scalar)
    const int nv    = (VOCAB - P) >> 2;           // aligned float4 count
    const int tailn = (VOCAB - P) & 3;            // tail elements (scalar)
    const float4* __restrict__ rp4 = reinterpret_cast<const float4*>(rp + P);

    // ---- Pass 1: streaming max (16 accumulators) + u16 upper-bound stash ----
    float4 M0 = make_float4(NEG_INF, NEG_INF, NEG_INF, NEG_INF);
    float4 M1 = M0, M2 = M0, M3 = M0;
    int v = tid;
    for (; v + 3 * T < nv; v += 4 * T) {
        float4 a = rp4[v];         float4 b = rp4[v + T];
        float4 c = rp4[v + 2 * T]; float4 d = rp4[v + 3 * T];
        stash4(su16, v,         a); stash4(su16, v + T,     b);
        stash4(su16, v + 2 * T, c); stash4(su16, v + 3 * T, d);
        M0 = max4(M0, a); M1 = max4(M1, b); M2 = max4(M2, c); M3 = max4(M3, d);
    }
    for (; v < nv; v += T) {
        float4 a = rp4[v];
        stash4(su16, v, a);
        M0 = max4(M0, a);
    }
    M0 = max4(max4(M0, M1), max4(M2, M3));
    smax[tid] = fmaxf(fmaxf(M0.x, M0.y), fmaxf(M0.z, M0.w));
    __syncthreads();

    // ---- Threshold: 10th largest of 256 per-thread maxima (valid lower bound
    // on the true 10th-largest row element: 10 largest maxima are distinct elems).
    if (tid < 32) {
        for (int r = 0; r < KSEL; ++r) {
            float bv = NEG_INF; int bp = tid;
            for (int c = tid; c < T; c += 32) {
                float x = smax[c];
                if (x > bv) { bv = x; bp = c; }
            }
            for (int off = 16; off; off >>= 1) {
                float ov = __shfl_down_sync(0xffffffffu, bv, off);
                int   op = __shfl_down_sync(0xffffffffu, bp, off);
                if (ov > bv) { bv = ov; bp = op; }
            }
            if (tid == 0) { smax[bp] = NEG_INF; *sthr = bv; }
            __syncwarp();
        }
    }
    __syncthreads();
    const float thr = *sthr;

    // ---- Pass 2: scan smem upper bounds; truncation toward +inf for v<=0 means
    // ub >= v, so (ub >= thr) is a superset of (v >= thr). Exact re-check later.
    for (v = tid; v < nv; v += T) {
        uint2 w = *reinterpret_cast<uint2*>(su16 + 4 * v);
        float f0 = __uint_as_float(w.x << 16);
        float f1 = __uint_as_float(w.x & 0xFFFF0000u);
        float f2 = __uint_as_float(w.y << 16);
        float f3 = __uint_as_float(w.y & 0xFFFF0000u);
        if (f0 >= thr) { unsigned p = atomicAdd(scount, 1u); if (p < CAP) cidx[p] = P + 4 * v; }
        if (f1 >= thr) { unsigned p = atomicAdd(scount, 1u); if (p < CAP) cidx[p] = P + 4 * v + 1; }
        if (f2 >= thr) { unsigned p = atomicAdd(scount, 1u); if (p < CAP) cidx[p] = P + 4 * v + 2; }
        if (f3 >= thr) { unsigned p = atomicAdd(scount, 1u); if (p < CAP) cidx[p] = P + 4 * v + 3; }
    }
    if (tid == 0) {          // head elements, exact test
        for (int i = 0; i < P; ++i) {
            float x = rp[i];
            if (x >= thr) { unsigned p = atomicAdd(scount, 1u); if (p < CAP) cidx[p] = i; }
        }
    }
    if (tid == 1) {          // tail elements, exact test
        for (int t = 0; t < tailn; ++t) {
            int i = P + 4 * nv + t;
            float x = rp[i];
            if (x >= thr) { unsigned p = atomicAdd(scount, 1u); if (p < CAP) cidx[p] = i; }
        }
    }
    __syncthreads();

    const unsigned cnt   = *scount;
    const int      stepv = step_ptr ? *step_ptr : KSEL;
    const float    base  = scores[row * score_last_dim + (stepv - 1)];

    if (cnt > CAP) {
        // Pathological mass-tie fallback: exact serial top-10 (never on random data).
        if (tid == 0) {
            float val[KSEL]; int idq[KSEL];
#pragma unroll
            for (int q = 0; q < KSEL; ++q) { val[q] = NEG_INF; idq[q] = IDX_INF; }
            for (int i = 0; i < VOCAB; ++i) {
                float x = rp[i];
                if (better(x, i, val[KSEL - 1], idq[KSEL - 1])) {
                    val[KSEL - 1] = x; idq[KSEL - 1] = i;
#pragma unroll
                    for (int q = KSEL - 1; q > 0; --q) {
                        if (better(val[q], idq[q], val[q - 1], idq[q - 1])) {
                            float tv = val[q]; val[q] = val[q - 1]; val[q - 1] = tv;
                            int   ti = idq[q]; idq[q] = idq[q - 1]; idq[q - 1] = ti;
                        }
                    }
                }
            }
#pragma unroll
            for (int r = 0; r < KSEL; ++r) {
                g_cand_val[row * KSEL + r] = (val[r] + base) - (float)(r + 1) * DIV_RATE;
                g_cand_idx[row * KSEL + r] = idq[r];
            }
        }
    } else {
        // Materialize exact values for survivors (scattered LDG, high MLP).
        for (unsigned c = tid; c < cnt; c += T) cval[c] = rp[cidx[c]];
        __syncthreads();

        // Warp-parallel stable top-10 over the candidate set.
        if (tid < 32) {
            for (int r = 0; r < KSEL; ++r) {
                float bv = NEG_INF; int bi = IDX_INF; int bp = -1;
                for (unsigned c = tid; c < cnt; c += 32) {
                    float x = cval[c]; int ix = cidx[c];
                    if (better(x, ix, bv, bi)) { bv = x; bi = ix; bp = (int)c; }
                }
                for (int off = 16; off; off >>= 1) {
                    float ov = __shfl_down_sync(0xffffffffu, bv, off);
                    int   oi = __shfl_down_sync(0xffffffffu, bi, off);
                    int   op = __shfl_down_sync(0xffffffffu, bp, off);
                    if (better(ov, oi, bv, bi)) { bv = ov; bi = oi; bp = op; }
                }
                if (tid == 0) {
                    // ((lprob + base) - penalty): reference op order -> bit-exact.
                    g_cand_val[row * KSEL + r] = (bv + base) - (float)(r + 1) * DIV_RATE;
                    g_cand_idx[row * KSEL + r] = bi;
                    cval[bp] = NEG_INF; cidx[bp] = IDX_INF;
                }
                __syncwarp();
            }
        }
    }

    // ---- Fused finisher: last beam-block of the batch does the 50->10 select ----
    int done = 0;
    if (tid == 0) {
        __threadfence();                               // release g_cand writes
        done = atomicAdd(&g_batch_done[batch], 1);
    }
    if (tid < 32) {
        done = __shfl_sync(0xffffffffu, done, 0);
        if (done == BEAM - 1) {
            __threadfence();                           // acquire peers' g_cand
            const int b50 = batch * BEAM * KSEL;
            float v0 = NEG_INF, v1 = NEG_INF;
            int   p0 = IDX_INF, p1 = IDX_INF;
            if (lane < BEAM * KSEL)      { v0 = __ldcg(&g_cand_val[b50 + lane]);      p0 = lane; }
            if (lane + 32 < BEAM * KSEL) { v1 = __ldcg(&g_cand_val[b50 + lane + 32]); p1 = lane + 32; }
            for (int r = 0; r < KSEL; ++r) {
                float bv; int bp;
                if (better(v0, p0, v1, p1)) { bv = v0; bp = p0; } else { bv = v1; bp = p1; }
                for (int off = 16; off; off >>= 1) {
                    float ov = __shfl_down_sync(0xffffffffu, bv, off);
                    int   op = __shfl_down_sync(0xffffffffu, bp, off);
                    if (better(ov, op, bv, bp)) { bv = ov; bp = op; }
                }
                bv = __shfl_sync(0xffffffffu, bv, 0);
                bp = __shfl_sync(0xffffffffu, bp, 0);
                if (lane == 0) {
                    out[batch * KSEL + r]                  = bv;                               // scores
                    out[BSZ * KSEL + batch * KSEL + r]     = (float)__ldcg(&g_cand_idx[b50 + bp]); // indices
                    out[2 * BSZ * KSEL + batch * KSEL + r] = (float)(bp / KSEL);               // beams
                }
                if (p0 == bp) { v0 = NEG_INF; p0 = IDX_INF; }
                if (p1 == bp) { v1 = NEG_INF; p1 = IDX_INF; }
            }
            if (lane == 0) atomicExch(&g_batch_done[batch], 0);   // reset for next replay
        }
    }
}

extern "C" void kernel_launch(void* const* d_in, const int* in_sizes, int n_in,
                              void* d_out, int out_size) {
    const float* lprobs = (const float*)d_in[0];
    const float* scores = (const float*)d_in[1];
    const int*   step   = (n_in >= 3) ? (const int*)d_in[2] : nullptr;
    const int score_last_dim = in_sizes[1] / ROWS;   // = 10

    cudaFuncSetAttribute(dss_kernel, cudaFuncAttributeMaxDynamicSharedMemorySize, DSM_BYTES);
    dss_kernel<<<ROWS, T, DSM_BYTES>>>(lprobs, scores, step, score_last_dim, (float*)d_out);
}

// round 8
// speedup vs baseline: 1.2025x; 1.2025x over previous
#include <cuda_runtime.h>
#include <cstdint>

// DiverseSiblingsSearch on GB300 — single-DRAM-pass threshold-select, fully fused.
// lprobs: (128, 5, 50257) f32, scores: (128, 5, 10) f32, step: int scalar (=10).
// Output (f32): final_scores (128,10) | final_indices (128,10) | final_beams (128,10).

#define BSZ     128
#define BEAM    5
#define VOCAB   50257
#define KSEL    10
#define ROWS    (BSZ * BEAM)
#define T       512
#define NWARP   (T / 32)
#define CAP     512
#define DIV_RATE 0.5f
#define NEG_INF __int_as_float(0xff800000u)
#define IDX_INF 0x7fffffff

// Dynamic smem: u16 row cache | smax[T] | cval[CAP] | cidx[CAP] | count/thr
#define SU16_BYTES 100544                      // 50260 u16, padded to 16B
#define DSM_BYTES  (SU16_BYTES + T * 4 + CAP * 4 + CAP * 4 + 64)

// Inter-block scratch (no allocations allowed).
__device__ float g_cand_val[ROWS * KSEL];
__device__ int   g_cand_idx[ROWS * KSEL];
__device__ int   g_batch_done[BSZ];            // zero-init; reset by finisher each replay

__device__ __forceinline__ bool better(float v1, int i1, float v2, int i2) {
    // JAX top_k stability: larger value wins; ties -> smaller index wins.
    return (v1 > v2) || (v1 == v2 && i1 < i2);
}

__device__ __forceinline__ float4 max4(float4 a, float4 b) {
    return make_float4(fmaxf(a.x, b.x), fmaxf(a.y, b.y), fmaxf(a.z, b.z), fmaxf(a.w, b.w));
}

// Pack high 16 bits of 4 floats (2x PRMT) and store 8B to smem.
__device__ __forceinline__ void stash4(uint16_t* su16, int v, float4 a) {
    uint32_t lo, hi;
    asm("prmt.b32 %0, %1, %2, 0x7632;" : "=r"(lo)
        : "r"(__float_as_uint(a.x)), "r"(__float_as_uint(a.y)));
    asm("prmt.b32 %0, %1, %2, 0x7632;" : "=r"(hi)
        : "r"(__float_as_uint(a.z)), "r"(__float_as_uint(a.w)));
    *reinterpret_cast<uint2*>(su16 + 4 * v) = make_uint2(lo, hi);
}

__global__ __launch_bounds__(T, 2)
void dss_kernel(const float* __restrict__ lprobs,
                const float* __restrict__ scores,
                const int* __restrict__ step_ptr,
                int score_last_dim,
                float* __restrict__ out) {
    extern __shared__ char dsm[];
    uint16_t* su16   = reinterpret_cast<uint16_t*>(dsm);
    float*    smax   = reinterpret_cast<float*>(dsm + SU16_BYTES);
    float*    cval   = smax + T;
    int*      cidx   = reinterpret_cast<int*>(cval + CAP);
    unsigned* scount = reinterpret_cast<unsigned*>(cidx + CAP);
    float*    sthr   = reinterpret_cast<float*>(scount + 1);

    const int row   = blockIdx.x;                 // row = batch * BEAM + beam
    const int batch = row / BEAM;
    const int tid   = threadIdx.x;
    const int lane  = tid & 31;
    const int wid   = tid >> 5;
    const float* __restrict__ rp = lprobs + (size_t)row * VOCAB;

    if (tid == 0) *scount = 0u;

    // Alignment peel: row*VOCAB mod 4 == row mod 4.
    const int P     = (4 - (row & 3)) & 3;        // head elements (scalar)
    const int nv    = (VOCAB - P) >> 2;           // aligned float4 count
    const int tailn = (VOCAB - P) & 3;            // tail elements (scalar)
    const float4* __restrict__ rp4 = reinterpret_cast<const float4*>(rp + P);

    // ---- Pass 1: streaming max (16 accumulators) + u16 upper-bound stash ----
    float4 M0 = make_float4(NEG_INF, NEG_INF, NEG_INF, NEG_INF);
    float4 M1 = M0, M2 = M0, M3 = M0;
    int v = tid;
    for (; v + 3 * T < nv; v += 4 * T) {
        float4 a = rp4[v];         float4 b = rp4[v + T];
        float4 c = rp4[v + 2 * T]; float4 d = rp4[v + 3 * T];
        stash4(su16, v,         a); stash4(su16, v + T,     b);
        stash4(su16, v + 2 * T, c); stash4(su16, v + 3 * T, d);
        M0 = max4(M0, a); M1 = max4(M1, b); M2 = max4(M2, c); M3 = max4(M3, d);
    }
    for (; v < nv; v += T) {
        float4 a = rp4[v];
        stash4(su16, v, a);
        M0 = max4(M0, a);
    }
    M0 = max4(max4(M0, M1), max4(M2, M3));
    float lmax = fmaxf(fmaxf(M0.x, M0.y), fmaxf(M0.z, M0.w));

    // ---- Threshold (parallel): each warp's top-2 of its 32 per-lane maxima
    // -> 2*NWARP = 32 distinct row elements; 10th largest of those is a valid
    // conservative lower bound on the row's true 10th-largest element.
    {
        float m = lmax;
        // round 1: warp max
        float w1 = m;
        for (int off = 16; off; off >>= 1) w1 = fmaxf(w1, __shfl_xor_sync(0xffffffffu, w1, off));
        // retire one holder of w1 (lowest lane)
        unsigned holders = __ballot_sync(0xffffffffu, m == w1);
        int first = __ffs(holders) - 1;
        float m2 = (lane == first) ? NEG_INF : m;
        float w2 = m2;
        for (int off = 16; off; off >>= 1) w2 = fmaxf(w2, __shfl_xor_sync(0xffffffffu, w2, off));
        if (lane == 0) { smax[wid] = w1; smax[NWARP + wid] = w2; }
    }
    __syncthreads();
    if (tid < 32) {
        float x = smax[tid];                        // 32 candidate values (2*NWARP = 32)
        float t = NEG_INF;
        for (int r = 0; r < KSEL; ++r) {
            float bv = x;
            for (int off = 16; off; off >>= 1) bv = fmaxf(bv, __shfl_xor_sync(0xffffffffu, bv, off));
            unsigned holders = __ballot_sync(0xffffffffu, x == bv);
            int first = __ffs(holders) - 1;
            if (lane == first) x = NEG_INF;         // retire one instance
            t = bv;
        }
        if (lane == 0) *sthr = t;
    }
    __syncthreads();
    const float thr = *sthr;

    // ---- Pass 2 (smem only): u16 truncation rounds toward +inf for v<=0, so
    // ub >= v and (ub >= thr) is a superset of (v >= thr). Exact re-check later.
    for (v = tid; v < nv; v += T) {
        uint2 w = *reinterpret_cast<uint2*>(su16 + 4 * v);
        float f0 = __uint_as_float(w.x << 16);
        float f1 = __uint_as_float(w.x & 0xFFFF0000u);
        float f2 = __uint_as_float(w.y << 16);
        float f3 = __uint_as_float(w.y & 0xFFFF0000u);
        if (f0 >= thr) { unsigned p = atomicAdd(scount, 1u); if (p < CAP) cidx[p] = P + 4 * v; }
        if (f1 >= thr) { unsigned p = atomicAdd(scount, 1u); if (p < CAP) cidx[p] = P + 4 * v + 1; }
        if (f2 >= thr) { unsigned p = atomicAdd(scount, 1u); if (p < CAP) cidx[p] = P + 4 * v + 2; }
        if (f3 >= thr) { unsigned p = atomicAdd(scount, 1u); if (p < CAP) cidx[p] = P + 4 * v + 3; }
    }
    if (tid == 0) {          // head elements, exact test
        for (int i = 0; i < P; ++i) {
            float x = rp[i];
            if (x >= thr) { unsigned p = atomicAdd(scount, 1u); if (p < CAP) cidx[p] = i; }
        }
    }
    if (tid == 1) {          // tail elements, exact test
        for (int q = 0; q < tailn; ++q) {
            int i = P + 4 * nv + q;
            float x = rp[i];
            if (x >= thr) { unsigned p = atomicAdd(scount, 1u); if (p < CAP) cidx[p] = i; }
        }
    }
    __syncthreads();

    const unsigned cnt   = *scount;
    const int      stepv = step_ptr ? *step_ptr : KSEL;
    const float    base  = scores[row * score_last_dim + (stepv - 1)];

    if (cnt > CAP) {
        // Pathological mass-tie fallback: exact serial top-10 (never on random data).
        if (tid == 0) {
            float val[KSEL]; int idq[KSEL];
#pragma unroll
            for (int q = 0; q < KSEL; ++q) { val[q] = NEG_INF; idq[q] = IDX_INF; }
            for (int i = 0; i < VOCAB; ++i) {
                float x = rp[i];
                if (better(x, i, val[KSEL - 1], idq[KSEL - 1])) {
                    val[KSEL - 1] = x; idq[KSEL - 1] = i;
#pragma unroll
                    for (int q = KSEL - 1; q > 0; --q) {
                        if (better(val[q], idq[q], val[q - 1], idq[q - 1])) {
                            float tv = val[q]; val[q] = val[q - 1]; val[q - 1] = tv;
                            int   ti = idq[q]; idq[q] = idq[q - 1]; idq[q - 1] = ti;
                        }
                    }
                }
            }
#pragma unroll
            for (int r = 0; r < KSEL; ++r) {
                g_cand_val[row * KSEL + r] = (val[r] + base) - (float)(r + 1) * DIV_RATE;
                g_cand_idx[row * KSEL + r] = idq[r];
            }
        }
    } else {
        // Materialize exact values for survivors (scattered LDG, high MLP).
        for (unsigned c = tid; c < cnt; c += T) cval[c] = rp[cidx[c]];
        __syncthreads();

        // Warp-parallel stable top-10 over the candidate set.
        if (tid < 32) {
            for (int r = 0; r < KSEL; ++r) {
                float bv = NEG_INF; int bi = IDX_INF; int bp = -1;
                for (unsigned c = tid; c < cnt; c += 32) {
                    float x = cval[c]; int ix = cidx[c];
                    if (better(x, ix, bv, bi)) { bv = x; bi = ix; bp = (int)c; }
                }
                for (int off = 16; off; off >>= 1) {
                    float ov = __shfl_down_sync(0xffffffffu, bv, off);
                    int   oi = __shfl_down_sync(0xffffffffu, bi, off);
                    int   op = __shfl_down_sync(0xffffffffu, bp, off);
                    if (better(ov, oi, bv, bi)) { bv = ov; bi = oi; bp = op; }
                }
                if (tid == 0) {
                    // ((lprob + base) - penalty): reference op order -> bit-exact.
                    g_cand_val[row * KSEL + r] = (bv + base) - (float)(r + 1) * DIV_RATE;
                    g_cand_idx[row * KSEL + r] = bi;
                    cval[bp] = NEG_INF; cidx[bp] = IDX_INF;
                }
                __syncwarp();
            }
        }
    }

    // ---- Fused finisher: last beam-block of the batch does the 50->10 select ----
    int done = 0;
    if (tid == 0) {
        __threadfence();                               // release g_cand writes
        done = atomicAdd(&g_batch_done[batch], 1);
    }
    if (tid < 32) {
        done = __shfl_sync(0xffffffffu, done, 0);
        if (done == BEAM - 1) {
            __threadfence();                           // acquire peers' g_cand
            const int b50 = batch * BEAM * KSEL;
            float v0 = NEG_INF, v1 = NEG_INF;
            int   p0 = IDX_INF, p1 = IDX_INF;
            if (lane < BEAM * KSEL)      { v0 = __ldcg(&g_cand_val[b50 + lane]);      p0 = lane; }
            if (lane + 32 < BEAM * KSEL) { v1 = __ldcg(&g_cand_val[b50 + lane + 32]); p1 = lane + 32; }
            for (int r = 0; r < KSEL; ++r) {
                float bv; int bp;
                if (better(v0, p0, v1, p1)) { bv = v0; bp = p0; } else { bv = v1; bp = p1; }
                for (int off = 16; off; off >>= 1) {
                    float ov = __shfl_down_sync(0xffffffffu, bv, off);
                    int   op = __shfl_down_sync(0xffffffffu, bp, off);
                    if (better(ov, op, bv, bp)) { bv = ov; bp = op; }
                }
                bv = __shfl_sync(0xffffffffu, bv, 0);
                bp = __shfl_sync(0xffffffffu, bp, 0);
                if (lane == 0) {
                    out[batch * KSEL + r]                  = bv;                                   // scores
                    out[BSZ * KSEL + batch * KSEL + r]     = (float)__ldcg(&g_cand_idx[b50 + bp]); // indices
                    out[2 * BSZ * KSEL + batch * KSEL + r] = (float)(bp / KSEL);                   // beams
                }
                if (p0 == bp) { v0 = NEG_INF; p0 = IDX_INF; }
                if (p1 == bp) { v1 = NEG_INF; p1 = IDX_INF; }
            }
            if (lane == 0) atomicExch(&g_batch_done[batch], 0);   // reset for next replay
        }
    }
}

extern "C" void kernel_launch(void* const* d_in, const int* in_sizes, int n_in,
                              void* d_out, int out_size) {
    const float* lprobs = (const float*)d_in[0];
    const float* scores = (const float*)d_in[1];
    const int*   step   = (n_in >= 3) ? (const int*)d_in[2] : nullptr;
    const int score_last_dim = in_sizes[1] / ROWS;   // = 10

    cudaFuncSetAttribute(dss_kernel, cudaFuncAttributeMaxDynamicSharedMemorySize, DSM_BYTES);
    dss_kernel<<<ROWS, T, DSM_BYTES>>>(lprobs, scores, step, score_last_dim, (float*)d_out);
}